// round 15
// baseline (speedup 1.0000x reference)
#include <cuda_runtime.h>
#include <cuda_fp16.h>
#include <stdint.h>

#define NN 32
#define TTOUT 63
#define TFULL 64
#define DD 64
#define KK 4
#define HH 256
#define SOH 256
#define SS 504
#define EE 992
#define MROWS (SS * NN)        // 16128
#define MTILES (MROWS / 128)   // 126
#define NTILES (SS * 8)        // 4032 (s, mt) tiles
#define NSM 148

// Scratch (__device__ globals; no allocation)
__device__ __half g_Qh[SS * KK * NN * HH];
__device__ __half g_Ph[SS * KK * NN * HH];
__device__ __half g_W2h[KK * HH * SOH];    // [k][h][c]
__device__ float  g_aggF[SS * NN * SOH];   // agg carry for k<3 (fp32)
__device__ __half g_W1h[64 * 2048];        // [d][k*512 + qp*256 + h]
__device__ __half g_Wf1h[320 * 256];
__device__ __half g_Wf2h[256 * 256];
__device__ __half g_Wf3h[256 * 256];       // padded: cols 64..255 zero
__device__ __half g_aug[MROWS * 320];      // [row][0:64)=X, [64:320)=agg

// ---------------------------------------------------------------------------
// helpers
// ---------------------------------------------------------------------------
__device__ __forceinline__ uint32_t smem_u32(const void* p) {
    uint32_t a;
    asm("{ .reg .u64 t; cvta.to.shared.u64 t, %1; cvt.u32.u64 %0, t; }"
        : "=r"(a) : "l"(p));
    return a;
}
__device__ __forceinline__ void ldsm_x4(uint32_t& r0, uint32_t& r1, uint32_t& r2,
                                        uint32_t& r3, uint32_t addr) {
    asm volatile("ldmatrix.sync.aligned.m8n8.x4.shared.b16 {%0,%1,%2,%3}, [%4];"
                 : "=r"(r0), "=r"(r1), "=r"(r2), "=r"(r3) : "r"(addr));
}
__device__ __forceinline__ void ldsm_x4_t(uint32_t& r0, uint32_t& r1, uint32_t& r2,
                                          uint32_t& r3, uint32_t addr) {
    asm volatile("ldmatrix.sync.aligned.m8n8.x4.trans.shared.b16 {%0,%1,%2,%3}, [%4];"
                 : "=r"(r0), "=r"(r1), "=r"(r2), "=r"(r3) : "r"(addr));
}
// fp32-accum HMMA (k1h/k3h)
__device__ __forceinline__ void mma16816(float* c, uint32_t a0, uint32_t a1,
                                         uint32_t a2, uint32_t a3,
                                         uint32_t b0, uint32_t b1) {
    asm volatile(
        "mma.sync.aligned.m16n8k16.row.col.f32.f16.f16.f32 "
        "{%0,%1,%2,%3}, {%4,%5,%6,%7}, {%8,%9}, {%0,%1,%2,%3};"
        : "+f"(c[0]), "+f"(c[1]), "+f"(c[2]), "+f"(c[3])
        : "r"(a0), "r"(a1), "r"(a2), "r"(a3), "r"(b0), "r"(b1));
}
// fp16-accum HMMA (k2): D/C are 2 regs of packed f16x2
__device__ __forceinline__ void mma16816h(uint32_t& c0, uint32_t& c1,
                                          uint32_t a0, uint32_t a1,
                                          uint32_t a2, uint32_t a3,
                                          uint32_t b0, uint32_t b1) {
    asm volatile(
        "mma.sync.aligned.m16n8k16.row.col.f16.f16.f16.f16 "
        "{%0,%1}, {%2,%3,%4,%5}, {%6,%7}, {%0,%1};"
        : "+r"(c0), "+r"(c1)
        : "r"(a0), "r"(a1), "r"(a2), "r"(a3), "r"(b0), "r"(b1));
}

// ---------------------------------------------------------------------------
// Converts
// ---------------------------------------------------------------------------
__global__ void c_w2(const float* __restrict__ W2) {
    int t = blockIdx.x * 256 + threadIdx.x;   // 65536
    float4 v = ((const float4*)W2)[t];
    __half2* dst = (__half2*)g_W2h;
    dst[t * 2 + 0] = __floats2half2_rn(v.x, v.y);
    dst[t * 2 + 1] = __floats2half2_rn(v.z, v.w);
}
__global__ void c_w1(const float* __restrict__ W1) {
    int idx = blockIdx.x * 256 + threadIdx.x;  // 131072
    int d = idx >> 11, c = idx & 2047;
    int k = c >> 9, qp = (c >> 8) & 1, h = c & 255;
    g_W1h[idx] = __float2half_rn(W1[(k * 128 + qp * 64 + d) * 256 + h]);
}
__global__ void c_wf(const float* __restrict__ Wf1, const float* __restrict__ Wf2,
                     const float* __restrict__ Wf3) {
    int idx = blockIdx.x * 256 + threadIdx.x;  // 212992
    if (idx < 81920) {
        g_Wf1h[idx] = __float2half_rn(Wf1[idx]);
    } else if (idx < 147456) {
        int i = idx - 81920;
        g_Wf2h[i] = __float2half_rn(Wf2[i]);
    } else {
        int i = idx - 147456;
        int r = i >> 8, c = i & 255;
        g_Wf3h[i] = (c < 64) ? __float2half_rn(Wf3[r * 64 + c]) : __float2half_rn(0.f);
    }
}
__global__ void c_x(const float* __restrict__ inp) {
    int idx = blockIdx.x * 256 + threadIdx.x;  // 1032192
    int gr = idx >> 6, d = idx & 63;
    int s = gr >> 5, n = gr & 31;
    int b = s / TTOUT, t = s - b * TTOUT;
    g_aug[gr * 320 + d] = __float2half_rn(inp[((b * NN + n) * TFULL + t) * DD + d]);
}

// ---------------------------------------------------------------------------
// K1h: Q|P GEMM (HMMA fp32-acc). Grid (126,8), Block 256.
// ---------------------------------------------------------------------------
__global__ __launch_bounds__(256) void k1h(const float* __restrict__ b1) {
    __shared__ __half As[128 * 64];
    __shared__ __half Bs[64 * 256];
    const int tid = threadIdx.x, lane = tid & 31, w = tid >> 5;
    const int mtile = blockIdx.x, nt = blockIdx.y;

    {
        const uint4* src = (const uint4*)g_aug;
        #pragma unroll
        for (int it = 0; it < 4; ++it) {
            int cid = it * 256 + tid; int r = cid >> 3, ch = cid & 7;
            uint4 v = src[(mtile * 128 + r) * 40 + ch];
            *(uint4*)((char*)As + r * 128 + ((ch ^ (r & 7)) << 4)) = v;
        }
    }
    {
        const uint4* src = (const uint4*)g_W1h;
        #pragma unroll
        for (int it = 0; it < 8; ++it) {
            int cid = it * 256 + tid; int r = cid >> 5, ch = cid & 31;
            uint4 v = src[r * 256 + nt * 32 + ch];
            *(uint4*)((char*)Bs + r * 512 + ((ch ^ (r & 7)) << 4)) = v;
        }
    }
    __syncthreads();

    const int wm = w >> 1, wn = w & 1;
    float acc[2][16][4];
    #pragma unroll
    for (int m2 = 0; m2 < 2; ++m2)
        #pragma unroll
        for (int nf = 0; nf < 16; ++nf)
            #pragma unroll
            for (int q = 0; q < 4; ++q) acc[m2][nf][q] = 0.f;

    const uint32_t As_b = smem_u32(As);
    const uint32_t Bs_b = smem_u32(Bs);
    const int arow = wm * 32 + (lane & 15);
    const int aswz = arow & 7;
    const int al16 = lane >> 4;
    const int koff = (lane & 7) + ((lane >> 3) & 1) * 8;
    const int kswz = koff & 7;
    const uint32_t brow0 = Bs_b + koff * 512;
    const int nfb = wn * 16 + (lane >> 4);

    #pragma unroll
    for (int ks = 0; ks < 4; ++ks) {
        uint32_t a0, a1, a2, a3, a4, a5, a6, a7;
        const int chnk = (ks * 2 + al16) ^ aswz;
        ldsm_x4(a0, a1, a2, a3, As_b + arow * 128 + (chnk << 4));
        ldsm_x4(a4, a5, a6, a7, As_b + (arow + 16) * 128 + (chnk << 4));
        const uint32_t brow = brow0 + ks * 8192;
        #pragma unroll
        for (int nfp = 0; nfp < 8; ++nfp) {
            uint32_t b0, b1v, b2v, b3v;
            ldsm_x4_t(b0, b1v, b2v, b3v, brow + (((nfb + nfp * 2) ^ kswz) << 4));
            mma16816(acc[0][2 * nfp],     a0, a1, a2, a3, b0, b1v);
            mma16816(acc[1][2 * nfp],     a4, a5, a6, a7, b0, b1v);
            mma16816(acc[0][2 * nfp + 1], a0, a1, a2, a3, b2v, b3v);
            mma16816(acc[1][2 * nfp + 1], a4, a5, a6, a7, b2v, b3v);
        }
    }

    const int r0 = lane >> 2;
    #pragma unroll
    for (int nf = 0; nf < 16; ++nf) {
        int C = nt * 256 + wn * 128 + nf * 8 + (lane & 3) * 2;
        int k = C >> 9, qp = (C >> 8) & 1, h = C & 255;
        float bb0 = 0.f, bb1 = 0.f;
        if (qp) { bb0 = b1[k * 256 + h]; bb1 = b1[k * 256 + h + 1]; }
        __half* dst = qp ? g_Ph : g_Qh;
        #pragma unroll
        for (int m2 = 0; m2 < 2; ++m2) {
            int r = wm * 32 + m2 * 16 + r0;
            int gr = mtile * 128 + r;
            int s = gr >> 5, n = gr & 31;
            *(__half2*)&dst[((s * KK + k) * NN + n) * HH + h] =
                __floats2half2_rn(acc[m2][nf][0] + bb0, acc[m2][nf][1] + bb1);
            int gr2 = gr + 8; int s2 = gr2 >> 5, n2 = gr2 & 31;
            *(__half2*)&dst[((s2 * KK + k) * NN + n2) * HH + h] =
                __floats2half2_rn(acc[m2][nf][2] + bb0, acc[m2][nf][3] + bb1);
        }
    }
}

// ---------------------------------------------------------------------------
// K2: persistent edge GEMM, fp16-accum HMMA with K=64 split-K chunks into
// fp32 master accumulators. Grid 148, Block 512 (16 warps), dyn smem 192 KB.
// Warp tile 32 rows x 64 cols: wm = w>>2 (rows/sender), wn = w&3 (cols).
// Same CTA owns tile t for all k -> agg carried in g_aggF for k<3;
// at k==3 the final value is written as fp16 directly into g_aug (k2b fused).
// ---------------------------------------------------------------------------
__global__ __launch_bounds__(512, 1)
void k2_edge(const float* __restrict__ rel, const float* __restrict__ b2) {
    extern __shared__ char sm2[];
    __half* As = (__half*)sm2;             // 128 x 256, 64 KB (h1)
    __half* Bs = (__half*)(sm2 + 65536);   // 256 x 256, 128 KB (W2[k])

    const int tid = threadIdx.x;
    const int lane = tid & 31, w = tid >> 5;
    const int p = blockIdx.x;
    const int wm = w >> 2, wn = w & 3;

    const uint32_t As_b = smem_u32(As);
    const uint32_t Bs_b = smem_u32(Bs);
    const int arow = wm * 32 + (lane & 15);
    const uint32_t aaddr0 = As_b + arow * 512;
    const uint32_t aaddr1 = As_b + (arow + 16) * 512;
    const int aswz = arow & 7;
    const int al16 = lane >> 4;
    const int koff = (lane & 7) + ((lane >> 3) & 1) * 8;
    const int kswz = koff & 7;
    const uint32_t brow0 = Bs_b + koff * 512;
    const int nfb = wn * 8 + (lane >> 4);
    const int r0 = lane >> 2;

    for (int k = 0; k < KK; ++k) {
        __syncthreads();
        {   // stage Bs = W2h[k]
            const uint4* src = (const uint4*)(g_W2h + k * HH * SOH);
            #pragma unroll
            for (int it = 0; it < 16; ++it) {
                int cid = it * 512 + tid;
                int row = cid >> 5, ch = cid & 31;
                *(uint4*)((char*)Bs + row * 512 + ((ch ^ (row & 7)) << 4)) = src[cid];
            }
        }
        for (int t = p; t < NTILES; t += NSM) {
            const int s = t >> 3, mt = t & 7;
            const int b = s / TTOUT;
            __syncthreads();
            {   // build As = relu(Q[j] + P'[i]); row lr = g*32+r; pad r==31 zero
                const int lr = tid >> 2;
                const int qh = tid & 3;
                const int g = lr >> 5, r = lr & 31;
                const int isn = mt * 4 + g;
                const bool valid = (r < 31);
                const uint4* qrow = nullptr;
                const uint4* prow = nullptr;
                if (valid) {
                    int j = (r < isn) ? r : r + 1;
                    qrow = (const uint4*)(g_Qh + ((s * KK + k) * NN + j) * HH);
                    prow = (const uint4*)(g_Ph + ((s * KK + k) * NN + isn) * HH);
                }
                const __half2 hz = __floats2half2_rn(0.f, 0.f);
                #pragma unroll
                for (int c = 0; c < 8; ++c) {
                    int ch = qh * 8 + c;
                    uint4 o;
                    if (valid) {
                        uint4 q = qrow[ch], pp = prow[ch];
                        __half2* qhp = (__half2*)&q;
                        __half2* php = (__half2*)&pp;
                        __half2* ohp = (__half2*)&o;
                        #pragma unroll
                        for (int e = 0; e < 4; ++e)
                            ohp[e] = __hmax2(__hadd2(qhp[e], php[e]), hz);
                    } else {
                        o.x = o.y = o.z = o.w = 0u;
                    }
                    *(uint4*)((char*)As + lr * 512 + ((ch ^ (lr & 7)) << 4)) = o;
                }
            }
            __syncthreads();

            // fp32 master accumulators
            float accf[2][8][4];
            #pragma unroll
            for (int m2 = 0; m2 < 2; ++m2)
                #pragma unroll
                for (int nf = 0; nf < 8; ++nf)
                    #pragma unroll
                    for (int q = 0; q < 4; ++q) accf[m2][nf][q] = 0.f;

            #pragma unroll
            for (int kc = 0; kc < 4; ++kc) {
                // fp16 chunk accumulators (packed f16x2 x2 per fragment)
                uint32_t acch[2][8][2];
                #pragma unroll
                for (int m2 = 0; m2 < 2; ++m2)
                    #pragma unroll
                    for (int nf = 0; nf < 8; ++nf) {
                        acch[m2][nf][0] = 0u; acch[m2][nf][1] = 0u;
                    }
                #pragma unroll
                for (int ki = 0; ki < 4; ++ki) {
                    const int ks = kc * 4 + ki;
                    uint32_t a0, a1, a2, a3, a4, a5, a6, a7;
                    const int chnk = (ks * 2 + al16) ^ aswz;
                    ldsm_x4(a0, a1, a2, a3, aaddr0 + (chnk << 4));
                    ldsm_x4(a4, a5, a6, a7, aaddr1 + (chnk << 4));
                    const uint32_t brow = brow0 + ks * 8192;
                    #pragma unroll
                    for (int nfp = 0; nfp < 4; ++nfp) {
                        uint32_t b0, b1v, b2v, b3v;
                        ldsm_x4_t(b0, b1v, b2v, b3v,
                                  brow + (((nfb + nfp * 2) ^ kswz) << 4));
                        mma16816h(acch[0][2*nfp][0],   acch[0][2*nfp][1],
                                  a0, a1, a2, a3, b0, b1v);
                        mma16816h(acch[1][2*nfp][0],   acch[1][2*nfp][1],
                                  a4, a5, a6, a7, b0, b1v);
                        mma16816h(acch[0][2*nfp+1][0], acch[0][2*nfp+1][1],
                                  a0, a1, a2, a3, b2v, b3v);
                        mma16816h(acch[1][2*nfp+1][0], acch[1][2*nfp+1][1],
                                  a4, a5, a6, a7, b2v, b3v);
                    }
                }
                // unpack chunk f16 -> fp32 masters (hidden under tensor pipe)
                #pragma unroll
                for (int m2 = 0; m2 < 2; ++m2)
                    #pragma unroll
                    for (int nf = 0; nf < 8; ++nf) {
                        float2 f0 = __half22float2(*(__half2*)&acch[m2][nf][0]);
                        float2 f1 = __half22float2(*(__half2*)&acch[m2][nf][1]);
                        accf[m2][nf][0] += f0.x; accf[m2][nf][1] += f0.y;
                        accf[m2][nf][2] += f1.x; accf[m2][nf][3] += f1.y;
                    }
            }

            // epilogue: h2 = relu(acc + b2) * rel, shuffle-reduce 32 rows
            const int isn = mt * 4 + wm;
            const float* relbase = rel + ((size_t)b * EE + isn * 31) * KK + k;
            float w00 = relbase[r0 * KK];
            float w01 = relbase[(r0 + 8) * KK];
            float w10 = relbase[(r0 + 16) * KK];
            float w11 = (r0 + 24 < 31) ? relbase[(r0 + 24) * KK] : 0.f;
            const float* b2k = b2 + k * SOH;
            const size_t gr = (size_t)s * NN + isn;
            float* aggout = g_aggF + gr * SOH;

            #pragma unroll
            for (int nf = 0; nf < 8; ++nf) {
                int c0 = wn * 64 + nf * 8 + (lane & 3) * 2;
                float bc0 = b2k[c0], bc1 = b2k[c0 + 1];
                float s0 = fmaxf(accf[0][nf][0] + bc0, 0.f) * w00
                         + fmaxf(accf[0][nf][2] + bc0, 0.f) * w01
                         + fmaxf(accf[1][nf][0] + bc0, 0.f) * w10
                         + fmaxf(accf[1][nf][2] + bc0, 0.f) * w11;
                float s1 = fmaxf(accf[0][nf][1] + bc1, 0.f) * w00
                         + fmaxf(accf[0][nf][3] + bc1, 0.f) * w01
                         + fmaxf(accf[1][nf][1] + bc1, 0.f) * w10
                         + fmaxf(accf[1][nf][3] + bc1, 0.f) * w11;
                s0 += __shfl_xor_sync(0xffffffffu, s0, 4);
                s0 += __shfl_xor_sync(0xffffffffu, s0, 8);
                s0 += __shfl_xor_sync(0xffffffffu, s0, 16);
                s1 += __shfl_xor_sync(0xffffffffu, s1, 4);
                s1 += __shfl_xor_sync(0xffffffffu, s1, 8);
                s1 += __shfl_xor_sync(0xffffffffu, s1, 16);
                if (lane < 4) {
                    if (k == 0) {
                        *(float2*)&aggout[c0] = make_float2(s0, s1);
                    } else if (k < KK - 1) {
                        float2 old = *(float2*)&aggout[c0];
                        *(float2*)&aggout[c0] = make_float2(old.x + s0, old.y + s1);
                    } else {
                        // final k: write fp16 aug directly (k2b fused)
                        float2 old = *(float2*)&aggout[c0];
                        *(__half2*)&g_aug[gr * 320 + 64 + c0] =
                            __floats2half2_rn(old.x + s0, old.y + s1);
                    }
                }
            }
        }
    }
}

// ---------------------------------------------------------------------------
// K3h: fused 3-layer MLP (HMMA fp32-acc). Grid 126, Block 256, smem 176 KB.
// ---------------------------------------------------------------------------
__global__ __launch_bounds__(256, 1)
void k3h(const float* __restrict__ bf1, const float* __restrict__ bf2,
         const float* __restrict__ bf3, const float* __restrict__ inp,
         float* __restrict__ out) {
    extern __shared__ char sm3[];
    __half* As = (__half*)sm3;
    __half* Bs = (__half*)(sm3 + 81920);
    __half* Hs = (__half*)(sm3 + 81920 + 32768);

    const int tid = threadIdx.x, lane = tid & 31, w = tid >> 5;
    const int wm = w >> 1, wn = w & 1;
    const int mtile = blockIdx.x;

    const uint32_t As_b = smem_u32(As);
    const uint32_t Bs_b = smem_u32(Bs);
    const uint32_t Hs_b = smem_u32(Hs);
    const int arow = wm * 32 + (lane & 15);
    const int aswz = arow & 7;
    const int al16 = lane >> 4;
    const int koff = (lane & 7) + ((lane >> 3) & 1) * 8;
    const int kswz = koff & 7;
    const int nfb = wn * 16 + (lane >> 4);
    const int r0 = lane >> 2;

    {
        const uint4* src = (const uint4*)g_aug;
        #pragma unroll
        for (int it = 0; it < 20; ++it) {
            int cid = it * 256 + tid;
            int r = cid / 40, ch = cid % 40;
            *(uint4*)((char*)As + r * 640 + ((ch ^ (r & 7)) << 4)) =
                src[(mtile * 128 + r) * 40 + ch];
        }
    }

    float acc[2][16][4];
    #define ZACC() do { _Pragma("unroll") for (int m2=0;m2<2;++m2) \
        _Pragma("unroll") for (int nf=0;nf<16;++nf) \
        _Pragma("unroll") for (int q=0;q<4;++q) acc[m2][nf][q]=0.f; } while(0)

    ZACC();
    for (int kc = 0; kc < 5; ++kc) {
        __syncthreads();
        {
            const uint4* src = (const uint4*)g_Wf1h + kc * 2048;
            #pragma unroll
            for (int it = 0; it < 8; ++it) {
                int cid = it * 256 + tid; int rr = cid >> 5, ch = cid & 31;
                *(uint4*)((char*)Bs + rr * 512 + ((ch ^ (rr & 7)) << 4)) = src[cid];
            }
        }
        __syncthreads();
        #pragma unroll
        for (int ki = 0; ki < 4; ++ki) {
            const int chnk = ((kc * 4 + ki) * 2 + al16) ^ aswz;
            uint32_t a0, a1, a2, a3, a4, a5, a6, a7;
            ldsm_x4(a0, a1, a2, a3, As_b + arow * 640 + (chnk << 4));
            ldsm_x4(a4, a5, a6, a7, As_b + (arow + 16) * 640 + (chnk << 4));
            const uint32_t brow = Bs_b + koff * 512 + ki * 8192;
            #pragma unroll
            for (int nfp = 0; nfp < 8; ++nfp) {
                uint32_t b0, b1v, b2v, b3v;
                ldsm_x4_t(b0, b1v, b2v, b3v, brow + (((nfb + nfp * 2) ^ kswz) << 4));
                mma16816(acc[0][2 * nfp],     a0, a1, a2, a3, b0, b1v);
                mma16816(acc[1][2 * nfp],     a4, a5, a6, a7, b0, b1v);
                mma16816(acc[0][2 * nfp + 1], a0, a1, a2, a3, b2v, b3v);
                mma16816(acc[1][2 * nfp + 1], a4, a5, a6, a7, b2v, b3v);
            }
        }
    }
    #pragma unroll
    for (int nf = 0; nf < 16; ++nf) {
        int c0 = wn * 128 + nf * 8 + (lane & 3) * 2;
        float bb0 = bf1[c0], bb1 = bf1[c0 + 1];
        #pragma unroll
        for (int m2 = 0; m2 < 2; ++m2) {
            int r = wm * 32 + m2 * 16 + r0;
            *(__half2*)((char*)Hs + r * 512 + (((c0 >> 3) ^ (r & 7)) << 4) + (c0 & 7) * 2) =
                __floats2half2_rn(fmaxf(acc[m2][nf][0] + bb0, 0.f),
                                  fmaxf(acc[m2][nf][1] + bb1, 0.f));
            int r2 = r + 8;
            *(__half2*)((char*)Hs + r2 * 512 + (((c0 >> 3) ^ (r2 & 7)) << 4) + (c0 & 7) * 2) =
                __floats2half2_rn(fmaxf(acc[m2][nf][2] + bb0, 0.f),
                                  fmaxf(acc[m2][nf][3] + bb1, 0.f));
        }
    }

    ZACC();
    for (int kc = 0; kc < 4; ++kc) {
        __syncthreads();
        {
            const uint4* src = (const uint4*)g_Wf2h + kc * 2048;
            #pragma unroll
            for (int it = 0; it < 8; ++it) {
                int cid = it * 256 + tid; int rr = cid >> 5, ch = cid & 31;
                *(uint4*)((char*)Bs + rr * 512 + ((ch ^ (rr & 7)) << 4)) = src[cid];
            }
        }
        __syncthreads();
        #pragma unroll
        for (int ki = 0; ki < 4; ++ki) {
            const int chnk = ((kc * 4 + ki) * 2 + al16) ^ aswz;
            uint32_t a0, a1, a2, a3, a4, a5, a6, a7;
            ldsm_x4(a0, a1, a2, a3, Hs_b + arow * 512 + (chnk << 4));
            ldsm_x4(a4, a5, a6, a7, Hs_b + (arow + 16) * 512 + (chnk << 4));
            const uint32_t brow = Bs_b + koff * 512 + ki * 8192;
            #pragma unroll
            for (int nfp = 0; nfp < 8; ++nfp) {
                uint32_t b0, b1v, b2v, b3v;
                ldsm_x4_t(b0, b1v, b2v, b3v, brow + (((nfb + nfp * 2) ^ kswz) << 4));
                mma16816(acc[0][2 * nfp],     a0, a1, a2, a3, b0, b1v);
                mma16816(acc[1][2 * nfp],     a4, a5, a6, a7, b0, b1v);
                mma16816(acc[0][2 * nfp + 1], a0, a1, a2, a3, b2v, b3v);
                mma16816(acc[1][2 * nfp + 1], a4, a5, a6, a7, b2v, b3v);
            }
        }
    }
    __syncthreads();
    #pragma unroll
    for (int nf = 0; nf < 16; ++nf) {
        int c0 = wn * 128 + nf * 8 + (lane & 3) * 2;
        float bb0 = bf2[c0], bb1 = bf2[c0 + 1];
        #pragma unroll
        for (int m2 = 0; m2 < 2; ++m2) {
            int r = wm * 32 + m2 * 16 + r0;
            *(__half2*)((char*)As + r * 512 + (((c0 >> 3) ^ (r & 7)) << 4) + (c0 & 7) * 2) =
                __floats2half2_rn(fmaxf(acc[m2][nf][0] + bb0, 0.f),
                                  fmaxf(acc[m2][nf][1] + bb1, 0.f));
            int r2 = r + 8;
            *(__half2*)((char*)As + r2 * 512 + (((c0 >> 3) ^ (r2 & 7)) << 4) + (c0 & 7) * 2) =
                __floats2half2_rn(fmaxf(acc[m2][nf][2] + bb0, 0.f),
                                  fmaxf(acc[m2][nf][3] + bb1, 0.f));
        }
    }

    ZACC();
    for (int kc = 0; kc < 4; ++kc) {
        __syncthreads();
        {
            const uint4* src = (const uint4*)g_Wf3h + kc * 2048;
            #pragma unroll
            for (int it = 0; it < 8; ++it) {
                int cid = it * 256 + tid; int rr = cid >> 5, ch = cid & 31;
                *(uint4*)((char*)Bs + rr * 512 + ((ch ^ (rr & 7)) << 4)) = src[cid];
            }
        }
        __syncthreads();
        #pragma unroll
        for (int ki = 0; ki < 4; ++ki) {
            const int chnk = ((kc * 4 + ki) * 2 + al16) ^ aswz;
            uint32_t a0, a1, a2, a3, a4, a5, a6, a7;
            ldsm_x4(a0, a1, a2, a3, As_b + arow * 512 + (chnk << 4));
            ldsm_x4(a4, a5, a6, a7, As_b + (arow + 16) * 512 + (chnk << 4));
            const uint32_t brow = Bs_b + koff * 512 + ki * 8192;
            #pragma unroll
            for (int nfp = 0; nfp < 8; ++nfp) {
                uint32_t b0, b1v, b2v, b3v;
                ldsm_x4_t(b0, b1v, b2v, b3v, brow + (((nfb + nfp * 2) ^ kswz) << 4));
                mma16816(acc[0][2 * nfp],     a0, a1, a2, a3, b0, b1v);
                mma16816(acc[1][2 * nfp],     a4, a5, a6, a7, b0, b1v);
                mma16816(acc[0][2 * nfp + 1], a0, a1, a2, a3, b2v, b3v);
                mma16816(acc[1][2 * nfp + 1], a4, a5, a6, a7, b2v, b3v);
            }
        }
    }
    if (wn == 0) {
        #pragma unroll
        for (int nf = 0; nf < 8; ++nf) {
            int c0 = nf * 8 + (lane & 3) * 2;
            float bb0 = bf3[c0], bb1 = bf3[c0 + 1];
            #pragma unroll
            for (int m2 = 0; m2 < 2; ++m2) {
                #pragma unroll
                for (int half = 0; half < 2; ++half) {
                    int r = wm * 32 + m2 * 16 + r0 + half * 8;
                    int gr = mtile * 128 + r;
                    int s = gr >> 5, n = gr & 31;
                    int b = s / TTOUT, t = s - b * TTOUT;
                    size_t xo = ((size_t)(b * NN + n) * TFULL + t) * DD + c0;
                    size_t oo = ((size_t)(b * NN + n) * TTOUT + t) * DD + c0;
                    float2 xv = *(const float2*)&inp[xo];
                    float v0 = acc[m2][nf][half * 2 + 0] + bb0 + xv.x;
                    float v1 = acc[m2][nf][half * 2 + 1] + bb1 + xv.y;
                    *(float2*)&out[oo] = make_float2(v0, v1);
                }
            }
        }
    }
    #undef ZACC
}

// ---------------------------------------------------------------------------
extern "C" void kernel_launch(void* const* d_in, const int* in_sizes, int n_in,
                              void* d_out, int out_size) {
    const float* inp = (const float*)d_in[0];
    const float* rel = (const float*)d_in[1];
    const float* W1  = (const float*)d_in[4];
    const float* b1  = (const float*)d_in[5];
    const float* W2  = (const float*)d_in[6];
    const float* b2  = (const float*)d_in[7];
    const float* Wf1 = (const float*)d_in[8];
    const float* bf1 = (const float*)d_in[9];
    const float* Wf2 = (const float*)d_in[10];
    const float* bf2 = (const float*)d_in[11];
    const float* Wf3 = (const float*)d_in[12];
    const float* bf3 = (const float*)d_in[13];
    float* out = (float*)d_out;

    cudaFuncSetAttribute(k2_edge, cudaFuncAttributeMaxDynamicSharedMemorySize, 196608);
    cudaFuncSetAttribute(k3h, cudaFuncAttributeMaxDynamicSharedMemorySize, 180224);

    c_w2<<<256, 256>>>(W2);
    c_w1<<<512, 256>>>(W1);
    c_wf<<<832, 256>>>(Wf1, Wf2, Wf3);
    c_x<<<4032, 256>>>(inp);
    k1h<<<dim3(MTILES, 8), 256>>>(b1);
    k2_edge<<<NSM, 512, 196608>>>(rel, b2);
    k3h<<<MTILES, 256, 180224>>>(bf1, bf2, bf3, inp, out);
}

// round 16
// speedup vs baseline: 1.0389x; 1.0389x over previous
#include <cuda_runtime.h>
#include <cuda_fp16.h>
#include <stdint.h>

#define NN 32
#define TTOUT 63
#define TFULL 64
#define DD 64
#define KK 4
#define HH 256
#define SOH 256
#define SS 504
#define EE 992
#define MROWS (SS * NN)        // 16128
#define MTILES (MROWS / 128)   // 126
#define NTILES (SS * 8)        // 4032 (s, mt) tiles
#define NSM 148

// Scratch (__device__ globals; no allocation)
__device__ __half g_Qh[SS * KK * NN * HH];
__device__ __half g_Ph[SS * KK * NN * HH];
__device__ __half g_W2h[KK * HH * SOH];    // [k][h][c]
__device__ float  g_aggF[SS * NN * SOH];   // agg carry for k<3 (fp32)
__device__ __half g_W1h[64 * 2048];        // [d][k*512 + qp*256 + h]
__device__ __half g_Wf1h[320 * 256];
__device__ __half g_Wf2h[256 * 256];
__device__ __half g_Wf3h[256 * 256];       // padded: cols 64..255 zero
__device__ __half g_aug[MROWS * 320];      // [row][0:64)=X, [64:320)=agg

// ---------------------------------------------------------------------------
// helpers
// ---------------------------------------------------------------------------
__device__ __forceinline__ uint32_t smem_u32(const void* p) {
    uint32_t a;
    asm("{ .reg .u64 t; cvta.to.shared.u64 t, %1; cvt.u32.u64 %0, t; }"
        : "=r"(a) : "l"(p));
    return a;
}
__device__ __forceinline__ void ldsm_x4(uint32_t& r0, uint32_t& r1, uint32_t& r2,
                                        uint32_t& r3, uint32_t addr) {
    asm volatile("ldmatrix.sync.aligned.m8n8.x4.shared.b16 {%0,%1,%2,%3}, [%4];"
                 : "=r"(r0), "=r"(r1), "=r"(r2), "=r"(r3) : "r"(addr));
}
__device__ __forceinline__ void ldsm_x4_t(uint32_t& r0, uint32_t& r1, uint32_t& r2,
                                          uint32_t& r3, uint32_t addr) {
    asm volatile("ldmatrix.sync.aligned.m8n8.x4.trans.shared.b16 {%0,%1,%2,%3}, [%4];"
                 : "=r"(r0), "=r"(r1), "=r"(r2), "=r"(r3) : "r"(addr));
}
// fp32-accum HMMA
__device__ __forceinline__ void mma16816(float* c, uint32_t a0, uint32_t a1,
                                         uint32_t a2, uint32_t a3,
                                         uint32_t b0, uint32_t b1) {
    asm volatile(
        "mma.sync.aligned.m16n8k16.row.col.f32.f16.f16.f32 "
        "{%0,%1,%2,%3}, {%4,%5,%6,%7}, {%8,%9}, {%0,%1,%2,%3};"
        : "+f"(c[0]), "+f"(c[1]), "+f"(c[2]), "+f"(c[3])
        : "r"(a0), "r"(a1), "r"(a2), "r"(a3), "r"(b0), "r"(b1));
}

// ---------------------------------------------------------------------------
// Merged weight convert: W2 | W1 | Wf1/2/3. Grid 1600, Block 256.
// ---------------------------------------------------------------------------
__global__ void c_weights(const float* __restrict__ W2, const float* __restrict__ W1,
                          const float* __restrict__ Wf1, const float* __restrict__ Wf2,
                          const float* __restrict__ Wf3) {
    int idx = blockIdx.x * 256 + threadIdx.x;   // 409600 total
    if (idx < 65536) {
        float4 v = ((const float4*)W2)[idx];
        __half2* dst = (__half2*)g_W2h;
        dst[idx * 2 + 0] = __floats2half2_rn(v.x, v.y);
        dst[idx * 2 + 1] = __floats2half2_rn(v.z, v.w);
    } else if (idx < 196608) {
        int i = idx - 65536;                     // 131072
        int d = i >> 11, c = i & 2047;
        int k = c >> 9, qp = (c >> 8) & 1, h = c & 255;
        g_W1h[i] = __float2half_rn(W1[(k * 128 + qp * 64 + d) * 256 + h]);
    } else {
        int i = idx - 196608;                    // 212992
        if (i < 81920) {
            g_Wf1h[i] = __float2half_rn(Wf1[i]);
        } else if (i < 147456) {
            int j = i - 81920;
            g_Wf2h[j] = __float2half_rn(Wf2[j]);
        } else {
            int j = i - 147456;
            int r = j >> 8, c = j & 255;
            g_Wf3h[j] = (c < 64) ? __float2half_rn(Wf3[r * 64 + c])
                                 : __float2half_rn(0.f);
        }
    }
}
__global__ void c_x(const float* __restrict__ inp) {
    int idx = blockIdx.x * 256 + threadIdx.x;  // 1032192
    int gr = idx >> 6, d = idx & 63;
    int s = gr >> 5, n = gr & 31;
    int b = s / TTOUT, t = s - b * TTOUT;
    g_aug[gr * 320 + d] = __float2half_rn(inp[((b * NN + n) * TFULL + t) * DD + d]);
}

// ---------------------------------------------------------------------------
// K1h: Q|P GEMM (HMMA fp32-acc). Grid (126,8), Block 256.
// ---------------------------------------------------------------------------
__global__ __launch_bounds__(256) void k1h(const float* __restrict__ b1) {
    __shared__ __half As[128 * 64];
    __shared__ __half Bs[64 * 256];
    const int tid = threadIdx.x, lane = tid & 31, w = tid >> 5;
    const int mtile = blockIdx.x, nt = blockIdx.y;

    {
        const uint4* src = (const uint4*)g_aug;
        #pragma unroll
        for (int it = 0; it < 4; ++it) {
            int cid = it * 256 + tid; int r = cid >> 3, ch = cid & 7;
            uint4 v = src[(mtile * 128 + r) * 40 + ch];
            *(uint4*)((char*)As + r * 128 + ((ch ^ (r & 7)) << 4)) = v;
        }
    }
    {
        const uint4* src = (const uint4*)g_W1h;
        #pragma unroll
        for (int it = 0; it < 8; ++it) {
            int cid = it * 256 + tid; int r = cid >> 5, ch = cid & 31;
            uint4 v = src[r * 256 + nt * 32 + ch];
            *(uint4*)((char*)Bs + r * 512 + ((ch ^ (r & 7)) << 4)) = v;
        }
    }
    __syncthreads();

    const int wm = w >> 1, wn = w & 1;
    float acc[2][16][4];
    #pragma unroll
    for (int m2 = 0; m2 < 2; ++m2)
        #pragma unroll
        for (int nf = 0; nf < 16; ++nf)
            #pragma unroll
            for (int q = 0; q < 4; ++q) acc[m2][nf][q] = 0.f;

    const uint32_t As_b = smem_u32(As);
    const uint32_t Bs_b = smem_u32(Bs);
    const int arow = wm * 32 + (lane & 15);
    const int aswz = arow & 7;
    const int al16 = lane >> 4;
    const int koff = (lane & 7) + ((lane >> 3) & 1) * 8;
    const int kswz = koff & 7;
    const uint32_t brow0 = Bs_b + koff * 512;
    const int nfb = wn * 16 + (lane >> 4);

    #pragma unroll
    for (int ks = 0; ks < 4; ++ks) {
        uint32_t a0, a1, a2, a3, a4, a5, a6, a7;
        const int chnk = (ks * 2 + al16) ^ aswz;
        ldsm_x4(a0, a1, a2, a3, As_b + arow * 128 + (chnk << 4));
        ldsm_x4(a4, a5, a6, a7, As_b + (arow + 16) * 128 + (chnk << 4));
        const uint32_t brow = brow0 + ks * 8192;
        #pragma unroll
        for (int nfp = 0; nfp < 8; ++nfp) {
            uint32_t b0, b1v, b2v, b3v;
            ldsm_x4_t(b0, b1v, b2v, b3v, brow + (((nfb + nfp * 2) ^ kswz) << 4));
            mma16816(acc[0][2 * nfp],     a0, a1, a2, a3, b0, b1v);
            mma16816(acc[1][2 * nfp],     a4, a5, a6, a7, b0, b1v);
            mma16816(acc[0][2 * nfp + 1], a0, a1, a2, a3, b2v, b3v);
            mma16816(acc[1][2 * nfp + 1], a4, a5, a6, a7, b2v, b3v);
        }
    }

    const int r0 = lane >> 2;
    #pragma unroll
    for (int nf = 0; nf < 16; ++nf) {
        int C = nt * 256 + wn * 128 + nf * 8 + (lane & 3) * 2;
        int k = C >> 9, qp = (C >> 8) & 1, h = C & 255;
        float bb0 = 0.f, bb1 = 0.f;
        if (qp) { bb0 = b1[k * 256 + h]; bb1 = b1[k * 256 + h + 1]; }
        __half* dst = qp ? g_Ph : g_Qh;
        #pragma unroll
        for (int m2 = 0; m2 < 2; ++m2) {
            int r = wm * 32 + m2 * 16 + r0;
            int gr = mtile * 128 + r;
            int s = gr >> 5, n = gr & 31;
            *(__half2*)&dst[((s * KK + k) * NN + n) * HH + h] =
                __floats2half2_rn(acc[m2][nf][0] + bb0, acc[m2][nf][1] + bb1);
            int gr2 = gr + 8; int s2 = gr2 >> 5, n2 = gr2 & 31;
            *(__half2*)&dst[((s2 * KK + k) * NN + n2) * HH + h] =
                __floats2half2_rn(acc[m2][nf][2] + bb0, acc[m2][nf][3] + bb1);
        }
    }
}

// ---------------------------------------------------------------------------
// K2: persistent edge GEMM (R6-proven fp32-acc HMMA core). Grid 148,
// Block 256 (8 warps), dyn smem 192 KB. Warp tile 32 rows x 128 cols.
// Same CTA owns tile t for all k -> agg carried in g_aggF for k<3;
// at k==3 the final value is written as fp16 directly into g_aug (k2b fused).
// ---------------------------------------------------------------------------
__global__ __launch_bounds__(256, 1)
void k2_edge(const float* __restrict__ rel, const float* __restrict__ b2) {
    extern __shared__ char sm2[];
    __half* As = (__half*)sm2;             // 128 x 256, 64 KB (h1)
    __half* Bs = (__half*)(sm2 + 65536);   // 256 x 256, 128 KB (W2[k])

    const int tid = threadIdx.x;
    const int lane = tid & 31, w = tid >> 5;
    const int p = blockIdx.x;
    const int wm = w >> 1, wn = w & 1;

    const uint32_t As_b = smem_u32(As);
    const uint32_t Bs_b = smem_u32(Bs);
    const int arow = wm * 32 + (lane & 15);
    const uint32_t aaddr0 = As_b + arow * 512;
    const uint32_t aaddr1 = As_b + (arow + 16) * 512;
    const int aswz = arow & 7;
    const int al16 = lane >> 4;
    const int koff = (lane & 7) + ((lane >> 3) & 1) * 8;
    const int kswz = koff & 7;
    const uint32_t brow0 = Bs_b + koff * 512;
    const int nfb = wn * 16 + (lane >> 4);
    const int r0 = lane >> 2;

    for (int k = 0; k < KK; ++k) {
        __syncthreads();
        {   // stage Bs = W2h[k]
            const uint4* src = (const uint4*)(g_W2h + k * HH * SOH);
            #pragma unroll
            for (int it = 0; it < 32; ++it) {
                int cid = it * 256 + tid;
                int row = cid >> 5, ch = cid & 31;
                *(uint4*)((char*)Bs + row * 512 + ((ch ^ (row & 7)) << 4)) = src[cid];
            }
        }
        for (int t = p; t < NTILES; t += NSM) {
            const int s = t >> 3, mt = t & 7;
            const int b = s / TTOUT;
            __syncthreads();
            {   // build As = relu(Q[j] + P'[i]); row lr = g*32+r; pad r==31 zero
                const int lr = tid >> 1;
                const int hh = tid & 1;
                const int g = lr >> 5, r = lr & 31;
                const int isn = mt * 4 + g;
                const bool valid = (r < 31);
                const uint4* qrow = nullptr;
                const uint4* prow = nullptr;
                if (valid) {
                    int j = (r < isn) ? r : r + 1;
                    qrow = (const uint4*)(g_Qh + ((s * KK + k) * NN + j) * HH);
                    prow = (const uint4*)(g_Ph + ((s * KK + k) * NN + isn) * HH);
                }
                const __half2 hz = __floats2half2_rn(0.f, 0.f);
                #pragma unroll
                for (int c = 0; c < 16; ++c) {
                    int ch = hh * 16 + c;
                    uint4 o;
                    if (valid) {
                        uint4 q = qrow[ch], pp = prow[ch];
                        __half2* qh = (__half2*)&q;
                        __half2* ph = (__half2*)&pp;
                        __half2* oh = (__half2*)&o;
                        #pragma unroll
                        for (int e = 0; e < 4; ++e)
                            oh[e] = __hmax2(__hadd2(qh[e], ph[e]), hz);
                    } else {
                        o.x = o.y = o.z = o.w = 0u;
                    }
                    *(uint4*)((char*)As + lr * 512 + ((ch ^ (lr & 7)) << 4)) = o;
                }
            }
            __syncthreads();

            float acc[2][16][4];
            #pragma unroll
            for (int m2 = 0; m2 < 2; ++m2)
                #pragma unroll
                for (int nf = 0; nf < 16; ++nf)
                    #pragma unroll
                    for (int q = 0; q < 4; ++q) acc[m2][nf][q] = 0.f;

            for (int ks = 0; ks < 16; ++ks) {
                uint32_t a0, a1, a2, a3, a4, a5, a6, a7;
                const int chnk = (ks * 2 + al16) ^ aswz;
                ldsm_x4(a0, a1, a2, a3, aaddr0 + (chnk << 4));
                ldsm_x4(a4, a5, a6, a7, aaddr1 + (chnk << 4));
                const uint32_t brow = brow0 + ks * 8192;
                #pragma unroll
                for (int nfp = 0; nfp < 8; ++nfp) {
                    uint32_t b0, b1v, b2v, b3v;
                    ldsm_x4_t(b0, b1v, b2v, b3v, brow + (((nfb + nfp * 2) ^ kswz) << 4));
                    mma16816(acc[0][2 * nfp],     a0, a1, a2, a3, b0, b1v);
                    mma16816(acc[1][2 * nfp],     a4, a5, a6, a7, b0, b1v);
                    mma16816(acc[0][2 * nfp + 1], a0, a1, a2, a3, b2v, b3v);
                    mma16816(acc[1][2 * nfp + 1], a4, a5, a6, a7, b2v, b3v);
                }
            }

            // epilogue: h2 = relu(acc + b2) * rel, shuffle-reduce 32 edge rows
            const int isn = mt * 4 + wm;
            const float* relbase = rel + ((size_t)b * EE + isn * 31) * KK + k;
            float w00 = relbase[r0 * KK];
            float w01 = relbase[(r0 + 8) * KK];
            float w10 = relbase[(r0 + 16) * KK];
            float w11 = (r0 + 24 < 31) ? relbase[(r0 + 24) * KK] : 0.f;
            const float* b2k = b2 + k * SOH;
            const size_t gr = (size_t)s * NN + isn;
            float* aggout = g_aggF + gr * SOH;

            #pragma unroll
            for (int nf = 0; nf < 16; ++nf) {
                int c0 = wn * 128 + nf * 8 + (lane & 3) * 2;
                float bc0 = b2k[c0], bc1 = b2k[c0 + 1];
                float s0 = fmaxf(acc[0][nf][0] + bc0, 0.f) * w00
                         + fmaxf(acc[0][nf][2] + bc0, 0.f) * w01
                         + fmaxf(acc[1][nf][0] + bc0, 0.f) * w10
                         + fmaxf(acc[1][nf][2] + bc0, 0.f) * w11;
                float s1 = fmaxf(acc[0][nf][1] + bc1, 0.f) * w00
                         + fmaxf(acc[0][nf][3] + bc1, 0.f) * w01
                         + fmaxf(acc[1][nf][1] + bc1, 0.f) * w10
                         + fmaxf(acc[1][nf][3] + bc1, 0.f) * w11;
                s0 += __shfl_xor_sync(0xffffffffu, s0, 4);
                s0 += __shfl_xor_sync(0xffffffffu, s0, 8);
                s0 += __shfl_xor_sync(0xffffffffu, s0, 16);
                s1 += __shfl_xor_sync(0xffffffffu, s1, 4);
                s1 += __shfl_xor_sync(0xffffffffu, s1, 8);
                s1 += __shfl_xor_sync(0xffffffffu, s1, 16);
                if (lane < 4) {
                    if (k == 0) {
                        *(float2*)&aggout[c0] = make_float2(s0, s1);
                    } else if (k < KK - 1) {
                        float2 old = *(float2*)&aggout[c0];
                        *(float2*)&aggout[c0] = make_float2(old.x + s0, old.y + s1);
                    } else {
                        // final k: write fp16 aug directly (k2b fused)
                        float2 old = *(float2*)&aggout[c0];
                        *(__half2*)&g_aug[gr * 320 + 64 + c0] =
                            __floats2half2_rn(old.x + s0, old.y + s1);
                    }
                }
            }
        }
    }
}

// ---------------------------------------------------------------------------
// K3h: fused 3-layer MLP (HMMA fp32-acc). Grid 126, Block 256, smem 176 KB.
// ---------------------------------------------------------------------------
__global__ __launch_bounds__(256, 1)
void k3h(const float* __restrict__ bf1, const float* __restrict__ bf2,
         const float* __restrict__ bf3, const float* __restrict__ inp,
         float* __restrict__ out) {
    extern __shared__ char sm3[];
    __half* As = (__half*)sm3;
    __half* Bs = (__half*)(sm3 + 81920);
    __half* Hs = (__half*)(sm3 + 81920 + 32768);

    const int tid = threadIdx.x, lane = tid & 31, w = tid >> 5;
    const int wm = w >> 1, wn = w & 1;
    const int mtile = blockIdx.x;

    const uint32_t As_b = smem_u32(As);
    const uint32_t Bs_b = smem_u32(Bs);
    const uint32_t Hs_b = smem_u32(Hs);
    const int arow = wm * 32 + (lane & 15);
    const int aswz = arow & 7;
    const int al16 = lane >> 4;
    const int koff = (lane & 7) + ((lane >> 3) & 1) * 8;
    const int kswz = koff & 7;
    const int nfb = wn * 16 + (lane >> 4);
    const int r0 = lane >> 2;

    {
        const uint4* src = (const uint4*)g_aug;
        #pragma unroll
        for (int it = 0; it < 20; ++it) {
            int cid = it * 256 + tid;
            int r = cid / 40, ch = cid % 40;
            *(uint4*)((char*)As + r * 640 + ((ch ^ (r & 7)) << 4)) =
                src[(mtile * 128 + r) * 40 + ch];
        }
    }

    float acc[2][16][4];
    #define ZACC() do { _Pragma("unroll") for (int m2=0;m2<2;++m2) \
        _Pragma("unroll") for (int nf=0;nf<16;++nf) \
        _Pragma("unroll") for (int q=0;q<4;++q) acc[m2][nf][q]=0.f; } while(0)

    ZACC();
    for (int kc = 0; kc < 5; ++kc) {
        __syncthreads();
        {
            const uint4* src = (const uint4*)g_Wf1h + kc * 2048;
            #pragma unroll
            for (int it = 0; it < 8; ++it) {
                int cid = it * 256 + tid; int rr = cid >> 5, ch = cid & 31;
                *(uint4*)((char*)Bs + rr * 512 + ((ch ^ (rr & 7)) << 4)) = src[cid];
            }
        }
        __syncthreads();
        #pragma unroll
        for (int ki = 0; ki < 4; ++ki) {
            const int chnk = ((kc * 4 + ki) * 2 + al16) ^ aswz;
            uint32_t a0, a1, a2, a3, a4, a5, a6, a7;
            ldsm_x4(a0, a1, a2, a3, As_b + arow * 640 + (chnk << 4));
            ldsm_x4(a4, a5, a6, a7, As_b + (arow + 16) * 640 + (chnk << 4));
            const uint32_t brow = Bs_b + koff * 512 + ki * 8192;
            #pragma unroll
            for (int nfp = 0; nfp < 8; ++nfp) {
                uint32_t b0, b1v, b2v, b3v;
                ldsm_x4_t(b0, b1v, b2v, b3v, brow + (((nfb + nfp * 2) ^ kswz) << 4));
                mma16816(acc[0][2 * nfp],     a0, a1, a2, a3, b0, b1v);
                mma16816(acc[1][2 * nfp],     a4, a5, a6, a7, b0, b1v);
                mma16816(acc[0][2 * nfp + 1], a0, a1, a2, a3, b2v, b3v);
                mma16816(acc[1][2 * nfp + 1], a4, a5, a6, a7, b2v, b3v);
            }
        }
    }
    #pragma unroll
    for (int nf = 0; nf < 16; ++nf) {
        int c0 = wn * 128 + nf * 8 + (lane & 3) * 2;
        float bb0 = bf1[c0], bb1 = bf1[c0 + 1];
        #pragma unroll
        for (int m2 = 0; m2 < 2; ++m2) {
            int r = wm * 32 + m2 * 16 + r0;
            *(__half2*)((char*)Hs + r * 512 + (((c0 >> 3) ^ (r & 7)) << 4) + (c0 & 7) * 2) =
                __floats2half2_rn(fmaxf(acc[m2][nf][0] + bb0, 0.f),
                                  fmaxf(acc[m2][nf][1] + bb1, 0.f));
            int r2 = r + 8;
            *(__half2*)((char*)Hs + r2 * 512 + (((c0 >> 3) ^ (r2 & 7)) << 4) + (c0 & 7) * 2) =
                __floats2half2_rn(fmaxf(acc[m2][nf][2] + bb0, 0.f),
                                  fmaxf(acc[m2][nf][3] + bb1, 0.f));
        }
    }

    ZACC();
    for (int kc = 0; kc < 4; ++kc) {
        __syncthreads();
        {
            const uint4* src = (const uint4*)g_Wf2h + kc * 2048;
            #pragma unroll
            for (int it = 0; it < 8; ++it) {
                int cid = it * 256 + tid; int rr = cid >> 5, ch = cid & 31;
                *(uint4*)((char*)Bs + rr * 512 + ((ch ^ (rr & 7)) << 4)) = src[cid];
            }
        }
        __syncthreads();
        #pragma unroll
        for (int ki = 0; ki < 4; ++ki) {
            const int chnk = ((kc * 4 + ki) * 2 + al16) ^ aswz;
            uint32_t a0, a1, a2, a3, a4, a5, a6, a7;
            ldsm_x4(a0, a1, a2, a3, Hs_b + arow * 512 + (chnk << 4));
            ldsm_x4(a4, a5, a6, a7, Hs_b + (arow + 16) * 512 + (chnk << 4));
            const uint32_t brow = Bs_b + koff * 512 + ki * 8192;
            #pragma unroll
            for (int nfp = 0; nfp < 8; ++nfp) {
                uint32_t b0, b1v, b2v, b3v;
                ldsm_x4_t(b0, b1v, b2v, b3v, brow + (((nfb + nfp * 2) ^ kswz) << 4));
                mma16816(acc[0][2 * nfp],     a0, a1, a2, a3, b0, b1v);
                mma16816(acc[1][2 * nfp],     a4, a5, a6, a7, b0, b1v);
                mma16816(acc[0][2 * nfp + 1], a0, a1, a2, a3, b2v, b3v);
                mma16816(acc[1][2 * nfp + 1], a4, a5, a6, a7, b2v, b3v);
            }
        }
    }
    __syncthreads();
    #pragma unroll
    for (int nf = 0; nf < 16; ++nf) {
        int c0 = wn * 128 + nf * 8 + (lane & 3) * 2;
        float bb0 = bf2[c0], bb1 = bf2[c0 + 1];
        #pragma unroll
        for (int m2 = 0; m2 < 2; ++m2) {
            int r = wm * 32 + m2 * 16 + r0;
            *(__half2*)((char*)As + r * 512 + (((c0 >> 3) ^ (r & 7)) << 4) + (c0 & 7) * 2) =
                __floats2half2_rn(fmaxf(acc[m2][nf][0] + bb0, 0.f),
                                  fmaxf(acc[m2][nf][1] + bb1, 0.f));
            int r2 = r + 8;
            *(__half2*)((char*)As + r2 * 512 + (((c0 >> 3) ^ (r2 & 7)) << 4) + (c0 & 7) * 2) =
                __floats2half2_rn(fmaxf(acc[m2][nf][2] + bb0, 0.f),
                                  fmaxf(acc[m2][nf][3] + bb1, 0.f));
        }
    }

    ZACC();
    for (int kc = 0; kc < 4; ++kc) {
        __syncthreads();
        {
            const uint4* src = (const uint4*)g_Wf3h + kc * 2048;
            #pragma unroll
            for (int it = 0; it < 8; ++it) {
                int cid = it * 256 + tid; int rr = cid >> 5, ch = cid & 31;
                *(uint4*)((char*)Bs + rr * 512 + ((ch ^ (rr & 7)) << 4)) = src[cid];
            }
        }
        __syncthreads();
        #pragma unroll
        for (int ki = 0; ki < 4; ++ki) {
            const int chnk = ((kc * 4 + ki) * 2 + al16) ^ aswz;
            uint32_t a0, a1, a2, a3, a4, a5, a6, a7;
            ldsm_x4(a0, a1, a2, a3, As_b + arow * 512 + (chnk << 4));
            ldsm_x4(a4, a5, a6, a7, As_b + (arow + 16) * 512 + (chnk << 4));
            const uint32_t brow = Bs_b + koff * 512 + ki * 8192;
            #pragma unroll
            for (int nfp = 0; nfp < 8; ++nfp) {
                uint32_t b0, b1v, b2v, b3v;
                ldsm_x4_t(b0, b1v, b2v, b3v, brow + (((nfb + nfp * 2) ^ kswz) << 4));
                mma16816(acc[0][2 * nfp],     a0, a1, a2, a3, b0, b1v);
                mma16816(acc[1][2 * nfp],     a4, a5, a6, a7, b0, b1v);
                mma16816(acc[0][2 * nfp + 1], a0, a1, a2, a3, b2v, b3v);
                mma16816(acc[1][2 * nfp + 1], a4, a5, a6, a7, b2v, b3v);
            }
        }
    }
    if (wn == 0) {
        #pragma unroll
        for (int nf = 0; nf < 8; ++nf) {
            int c0 = nf * 8 + (lane & 3) * 2;
            float bb0 = bf3[c0], bb1 = bf3[c0 + 1];
            #pragma unroll
            for (int m2 = 0; m2 < 2; ++m2) {
                #pragma unroll
                for (int half = 0; half < 2; ++half) {
                    int r = wm * 32 + m2 * 16 + r0 + half * 8;
                    int gr = mtile * 128 + r;
                    int s = gr >> 5, n = gr & 31;
                    int b = s / TTOUT, t = s - b * TTOUT;
                    size_t xo = ((size_t)(b * NN + n) * TFULL + t) * DD + c0;
                    size_t oo = ((size_t)(b * NN + n) * TTOUT + t) * DD + c0;
                    float2 xv = *(const float2*)&inp[xo];
                    float v0 = acc[m2][nf][half * 2 + 0] + bb0 + xv.x;
                    float v1 = acc[m2][nf][half * 2 + 1] + bb1 + xv.y;
                    *(float2*)&out[oo] = make_float2(v0, v1);
                }
            }
        }
    }
    #undef ZACC
}

// ---------------------------------------------------------------------------
extern "C" void kernel_launch(void* const* d_in, const int* in_sizes, int n_in,
                              void* d_out, int out_size) {
    const float* inp = (const float*)d_in[0];
    const float* rel = (const float*)d_in[1];
    const float* W1  = (const float*)d_in[4];
    const float* b1  = (const float*)d_in[5];
    const float* W2  = (const float*)d_in[6];
    const float* b2  = (const float*)d_in[7];
    const float* Wf1 = (const float*)d_in[8];
    const float* bf1 = (const float*)d_in[9];
    const float* Wf2 = (const float*)d_in[10];
    const float* bf2 = (const float*)d_in[11];
    const float* Wf3 = (const float*)d_in[12];
    const float* bf3 = (const float*)d_in[13];
    float* out = (float*)d_out;

    cudaFuncSetAttribute(k2_edge, cudaFuncAttributeMaxDynamicSharedMemorySize, 196608);
    cudaFuncSetAttribute(k3h, cudaFuncAttributeMaxDynamicSharedMemorySize, 180224);

    c_weights<<<1600, 256>>>(W2, W1, Wf1, Wf2, Wf3);
    c_x<<<4032, 256>>>(inp);
    k1h<<<dim3(MTILES, 8), 256>>>(b1);
    k2_edge<<<NSM, 256, 196608>>>(rel, b2);
    k3h<<<MTILES, 256, 180224>>>(bf1, bf2, bf3, inp, out);
}